// round 3
// baseline (speedup 1.0000x reference)
#include <cuda_runtime.h>

// ResidualDenseBlock: out = scan_{l=0..63}( tanh(out @ W[l]^T + b[l]) * m[l] + out ) * sum(gates)
// x: [BATCH, 2] f32; W: [64,2,2]; b: [64,2]; masks: [64]; gates: [64]
//
// MUFU-bound design: hardware tanh.approx.f32 (1 MUFU op), 4 rows per thread,
// weights staged in shared (broadcast LDS), float4 coalesced I/O.

#define LAYERS  64
#define ROWS_PER_THREAD 4
#define TPB     256

__device__ __forceinline__ float tanh_fast(float x) {
    float y;
    asm("tanh.approx.f32 %0, %1;" : "=f"(y) : "f"(x));
    return y;
}

__global__ __launch_bounds__(TPB)
void rdb_kernel(const float4* __restrict__ x,
                const float*  __restrict__ W,
                const float*  __restrict__ b,
                const float*  __restrict__ masks,
                const float*  __restrict__ gates,
                float4* __restrict__ out,
                long long nfloat4)   // number of float4 elements = BATCH/2
{
    __shared__ float4 sW[LAYERS];   // w00, w01, w10, w11
    __shared__ float4 sB[LAYERS];   // b0, b1, mask, unused
    __shared__ float  sG;

    const int tid = threadIdx.x;

    if (tid < LAYERS) {
        sW[tid] = make_float4(W[tid * 4 + 0], W[tid * 4 + 1],
                              W[tid * 4 + 2], W[tid * 4 + 3]);
        sB[tid] = make_float4(b[tid * 2 + 0], b[tid * 2 + 1],
                              masks[tid], 0.0f);
    }
    if (tid == 0) {
        float s = 0.0f;
        #pragma unroll
        for (int i = 0; i < LAYERS; i++) s += gates[i];
        sG = s;
    }
    __syncthreads();

    // Each thread handles 4 rows = 2 float4 (x0,y0,x1,y1 packing).
    const long long gt = (long long)blockIdx.x * TPB + tid;
    const long long f4base = gt * 2;
    if (f4base >= nfloat4) return;
    const bool have2 = (f4base + 1) < nfloat4;

    float4 a = x[f4base];
    float4 c = have2 ? x[f4base + 1] : make_float4(0.f, 0.f, 0.f, 0.f);

    // 8 live values: (a.x,a.y) (a.z,a.w) (c.x,c.y) (c.z,c.w) — 4 rows.
    #pragma unroll 4
    for (int l = 0; l < LAYERS; l++) {
        const float4 w = sW[l];
        const float4 p = sB[l];
        // row 0
        float t0 = tanh_fast(fmaf(w.x, a.x, fmaf(w.y, a.y, p.x)));
        float t1 = tanh_fast(fmaf(w.z, a.x, fmaf(w.w, a.y, p.y)));
        // row 1
        float t2 = tanh_fast(fmaf(w.x, a.z, fmaf(w.y, a.w, p.x)));
        float t3 = tanh_fast(fmaf(w.z, a.z, fmaf(w.w, a.w, p.y)));
        // row 2
        float t4 = tanh_fast(fmaf(w.x, c.x, fmaf(w.y, c.y, p.x)));
        float t5 = tanh_fast(fmaf(w.z, c.x, fmaf(w.w, c.y, p.y)));
        // row 3
        float t6 = tanh_fast(fmaf(w.x, c.z, fmaf(w.y, c.w, p.x)));
        float t7 = tanh_fast(fmaf(w.z, c.z, fmaf(w.w, c.w, p.y)));

        a.x = fmaf(p.z, t0, a.x);
        a.y = fmaf(p.z, t1, a.y);
        a.z = fmaf(p.z, t2, a.z);
        a.w = fmaf(p.z, t3, a.w);
        c.x = fmaf(p.z, t4, c.x);
        c.y = fmaf(p.z, t5, c.y);
        c.z = fmaf(p.z, t6, c.z);
        c.w = fmaf(p.z, t7, c.w);
    }

    const float g = sG;
    a.x *= g; a.y *= g; a.z *= g; a.w *= g;
    c.x *= g; c.y *= g; c.z *= g; c.w *= g;

    out[f4base] = a;
    if (have2) out[f4base + 1] = c;
}

extern "C" void kernel_launch(void* const* d_in, const int* in_sizes, int n_in,
                              void* d_out, int out_size)
{
    const float4* x     = (const float4*)d_in[0];
    const float*  W     = (const float*) d_in[1];
    const float*  b     = (const float*) d_in[2];
    const float*  masks = (const float*) d_in[3];
    const float*  gates = (const float*) d_in[4];
    float4* out = (float4*)d_out;

    const long long nfloat = (long long)in_sizes[0];      // BATCH * 2
    const long long nfloat4 = nfloat / 4;                 // BATCH / 2
    const long long threads = (nfloat4 + 1) / 2;          // 2 float4 per thread
    const int blocks = (int)((threads + TPB - 1) / TPB);
    rdb_kernel<<<blocks, TPB>>>(x, W, b, masks, gates, out, nfloat4);
}

// round 4
// speedup vs baseline: 1.0461x; 1.0461x over previous
#include <cuda_runtime.h>

// ResidualDenseBlock: out = scan_{l=0..63}( tanh(out @ W[l]^T + b[l]) * m[l] + out ) * sum(gates)
//
// MUFU-bound. R4: cut MUFU work 8->6 insts/layer/warp by evaluating rows 2,3
// with tanh.approx.f16x2 (2 tanh per MUFU op); rows 0,1 stay exact f32 tanh.
// All layer math uses packed fma.rn.f32x2 on row-pair state (b64 regs).

#define LAYERS  64
#define TPB     256

typedef unsigned long long u64;

__device__ __forceinline__ float tanh_f32(float x) {
    float y;
    asm("tanh.approx.f32 %0, %1;" : "=f"(y) : "f"(x));
    return y;
}
__device__ __forceinline__ unsigned tanh_h2(unsigned h) {
    unsigned r;
    asm("tanh.approx.f16x2 %0, %1;" : "=r"(r) : "r"(h));
    return r;
}
// d = { hi = cvt(a), lo = cvt(b) }
__device__ __forceinline__ unsigned pack_h2(float hi, float lo) {
    unsigned r;
    asm("cvt.rn.f16x2.f32 %0, %1, %2;" : "=r"(r) : "f"(hi), "f"(lo));
    return r;
}
__device__ __forceinline__ void unpack_h2(float& lo, float& hi, unsigned h) {
    asm("{.reg .b16 l, u;\n\t"
        " mov.b32 {l, u}, %2;\n\t"
        " cvt.f32.f16 %0, l;\n\t"
        " cvt.f32.f16 %1, u;}"
        : "=f"(lo), "=f"(hi) : "r"(h));
}
__device__ __forceinline__ u64 fma2(u64 a, u64 b, u64 c) {
    u64 d;
    asm("fma.rn.f32x2 %0, %1, %2, %3;" : "=l"(d) : "l"(a), "l"(b), "l"(c));
    return d;
}
__device__ __forceinline__ u64 mul2(u64 a, u64 b) {
    u64 d;
    asm("mul.rn.f32x2 %0, %1, %2;" : "=l"(d) : "l"(a), "l"(b));
    return d;
}
__device__ __forceinline__ u64 pk2(float lo, float hi) {
    u64 d;
    asm("mov.b64 %0, {%1, %2};" : "=l"(d) : "f"(lo), "f"(hi));
    return d;
}
__device__ __forceinline__ void up2(float& lo, float& hi, u64 s) {
    asm("mov.b64 {%0, %1}, %2;" : "=f"(lo), "=f"(hi) : "l"(s));
}

struct __align__(16) LayerP {
    u64 w00, w01, w10, w11, b0, b1, m, pad;   // each holds (v, v) broadcast pair
};

__global__ __launch_bounds__(TPB)
void rdb_kernel(const float4* __restrict__ x,
                const float*  __restrict__ W,
                const float*  __restrict__ b,
                const float*  __restrict__ masks,
                const float*  __restrict__ gates,
                float4* __restrict__ out,
                long long nfloat4)
{
    __shared__ LayerP sP[LAYERS];
    __shared__ float  sG;

    const int tid = threadIdx.x;
    if (tid < LAYERS) {
        float w00 = W[tid * 4 + 0], w01 = W[tid * 4 + 1];
        float w10 = W[tid * 4 + 2], w11 = W[tid * 4 + 3];
        float b0 = b[tid * 2 + 0], b1 = b[tid * 2 + 1];
        float m = masks[tid];
        LayerP p;
        p.w00 = pk2(w00, w00); p.w01 = pk2(w01, w01);
        p.w10 = pk2(w10, w10); p.w11 = pk2(w11, w11);
        p.b0  = pk2(b0, b0);   p.b1  = pk2(b1, b1);
        p.m   = pk2(m, m);     p.pad = 0;
        sP[tid] = p;
    }
    if (tid == 0) {
        float s = 0.0f;
        #pragma unroll
        for (int i = 0; i < LAYERS; i++) s += gates[i];
        sG = s;
    }
    __syncthreads();

    const long long gt = (long long)blockIdx.x * TPB + tid;
    const long long f4base = gt * 2;
    if (f4base >= nfloat4) return;
    const bool have2 = (f4base + 1) < nfloat4;

    float4 a = x[f4base];                                   // rows 0,1: (x0,y0,x1,y1)
    float4 c = have2 ? x[f4base + 1] : make_float4(0,0,0,0); // rows 2,3

    // Row-pair state in packed f32x2:
    u64 Xa = pk2(a.x, a.z), Ya = pk2(a.y, a.w);   // rows 0,1  (exact f32 tanh)
    u64 Xc = pk2(c.x, c.z), Yc = pk2(c.y, c.w);   // rows 2,3  (f16x2 tanh)

    #pragma unroll 4
    for (int l = 0; l < LAYERS; l++) {
        const LayerP p = sP[l];

        // ---- pair A (rows 0,1): exact f32 tanh ----
        u64 argA0 = fma2(p.w00, Xa, fma2(p.w01, Ya, p.b0));
        u64 argA1 = fma2(p.w10, Xa, fma2(p.w11, Ya, p.b1));
        {
            float a0, a1, b0f, b1f;
            up2(a0, a1, argA0);
            up2(b0f, b1f, argA1);
            u64 tX = pk2(tanh_f32(a0), tanh_f32(a1));
            u64 tY = pk2(tanh_f32(b0f), tanh_f32(b1f));
            Xa = fma2(p.m, tX, Xa);
            Ya = fma2(p.m, tY, Ya);
        }

        // ---- pair C (rows 2,3): packed f16x2 tanh ----
        u64 argC0 = fma2(p.w00, Xc, fma2(p.w01, Yc, p.b0));
        u64 argC1 = fma2(p.w10, Xc, fma2(p.w11, Yc, p.b1));
        {
            float a0, a1, b0f, b1f;
            up2(a0, a1, argC0);
            up2(b0f, b1f, argC1);
            unsigned hX = tanh_h2(pack_h2(a1, a0));
            unsigned hY = tanh_h2(pack_h2(b1f, b0f));
            float tx0, tx1, ty0, ty1;
            unpack_h2(tx0, tx1, hX);
            unpack_h2(ty0, ty1, hY);
            Xc = fma2(p.m, pk2(tx0, tx1), Xc);
            Yc = fma2(p.m, pk2(ty0, ty1), Yc);
        }
    }

    const float g = sG;
    const u64 g2 = pk2(g, g);
    Xa = mul2(g2, Xa); Ya = mul2(g2, Ya);
    Xc = mul2(g2, Xc); Yc = mul2(g2, Yc);

    float x0, x1, y0, y1;
    up2(x0, x1, Xa); up2(y0, y1, Ya);
    out[f4base] = make_float4(x0, y0, x1, y1);
    if (have2) {
        up2(x0, x1, Xc); up2(y0, y1, Yc);
        out[f4base + 1] = make_float4(x0, y0, x1, y1);
    }
}

extern "C" void kernel_launch(void* const* d_in, const int* in_sizes, int n_in,
                              void* d_out, int out_size)
{
    const float4* x     = (const float4*)d_in[0];
    const float*  W     = (const float*) d_in[1];
    const float*  b     = (const float*) d_in[2];
    const float*  masks = (const float*) d_in[3];
    const float*  gates = (const float*) d_in[4];
    float4* out = (float4*)d_out;

    const long long nfloat  = (long long)in_sizes[0];   // BATCH * 2
    const long long nfloat4 = nfloat / 4;               // BATCH / 2
    const long long threads = (nfloat4 + 1) / 2;
    const int blocks = (int)((threads + TPB - 1) / TPB);
    rdb_kernel<<<blocks, TPB>>>(x, W, b, masks, gates, out, nfloat4);
}